// round 2
// baseline (speedup 1.0000x reference)
#include <cuda_runtime.h>
#include <math_constants.h>

// Problem constants (fixed for this dataset problem)
#define BATCH 2
#define NPTS  2048
#define BN    (BATCH * NPTS)   // 4096 total points
#define CF    32               // feature channels
#define CP    35               // C + 3
#define DIM   32               // D
#define KNN   36               // k
#define DD    1024             // D*D
#define PQW   2048             // P(1024) | Q(1024)

// ---------------- device scratch (no runtime allocation allowed) -------------
__device__ float g_pre[BN * CP];       // [4096,35] concat(feature,xyz)
__device__ float g_d2[BN];             // squared norms of xyz
__device__ float g_v[BN * DIM];        // relu(pre @ W_v + b_v)
__device__ int   g_idx[BN * KNN];      // global neighbor row indices
__device__ float g_WCAT[CP * PQW];     // [35, 2048] = [W1 | W2-W1]
__device__ float g_PQ[BN * PQW];       // [4096, 2048] = [P | Q] (32 MB)

// ---------------- helpers ----------------------------------------------------
__device__ __forceinline__ unsigned int fkey(float v) {
    unsigned int u = __float_as_uint(v);
    return (u & 0x80000000u) ? ~u : (u | 0x80000000u);   // order-preserving map
}

// ---------------- prep: pre = concat(feature,xyz); d2 = sum(xyz^2) -----------
__global__ void prep_pre_d2(const float* __restrict__ feature,
                            const float* __restrict__ xyz) {
    int gid = blockIdx.x * blockDim.x + threadIdx.x;
    if (gid < BN * CP) {
        int n = gid / CP, c = gid - n * CP;
        g_pre[gid] = (c < CF) ? feature[n * CF + c] : xyz[n * 3 + (c - CF)];
    }
    if (gid < BN) {
        float x = xyz[gid * 3 + 0], y = xyz[gid * 3 + 1], z = xyz[gid * 3 + 2];
        // match jnp.sum(xyz*xyz, -1): per-element square then sum (no fma fuse)
        g_d2[gid] = __fadd_rn(__fadd_rn(__fmul_rn(x, x), __fmul_rn(y, y)),
                              __fmul_rn(z, z));
    }
}

// ---------------- prep: WCAT = [W1 | W2 - W1] --------------------------------
__global__ void prep_wcat(const float* __restrict__ W_r) {
    int gid = blockIdx.x * blockDim.x + threadIdx.x;
    if (gid < CP * PQW) {
        int c = gid / PQW, j = gid - c * PQW;
        if (j < DD) {
            g_WCAT[gid] = W_r[c * DD + j];
        } else {
            int jj = j - DD;
            g_WCAT[gid] = W_r[(CP + c) * DD + jj] - W_r[c * DD + jj];
        }
    }
}

// ---------------- prep: v = relu(pre @ W_v + b_v) ----------------------------
__global__ void prep_v(const float* __restrict__ W_v,
                       const float* __restrict__ b_v) {
    int gid = blockIdx.x * blockDim.x + threadIdx.x;
    if (gid < BN * DIM) {
        int n = gid >> 5, d = gid & 31;
        const float* pr = g_pre + n * CP;
        float acc = b_v[d];
#pragma unroll
        for (int c = 0; c < CP; c++)
            acc = fmaf(pr[c], W_v[c * DIM + d], acc);
        g_v[gid] = fmaxf(acc, 0.0f);
    }
}

// ---------------- PQ = pre @ WCAT (+ b_r on Q half) --------------------------
// CTA: 16 rows x 1024 cols; 256 threads; thread owns 4 CONSECUTIVE cols x 16
// rows -> WCAT read as LDG.128, PQ written as STG.128 (LSU-floor friendly).
__global__ void __launch_bounds__(256) gemm_pq(const float* __restrict__ b_r) {
    __shared__ float sPre[16][CP + 1];
    int t = threadIdx.x;
    int rb = blockIdx.y * 16;
    for (int q = t; q < 16 * CP; q += 256) {
        int r = q / CP, c = q - r * CP;
        sPre[r][c] = g_pre[(rb + r) * CP + c];
    }
    __syncthreads();

    int j0 = blockIdx.x * 1024 + t * 4;    // 4 consecutive columns
    float acc[16][4];
#pragma unroll
    for (int r = 0; r < 16; r++)
#pragma unroll
        for (int q = 0; q < 4; q++) acc[r][q] = 0.0f;

    for (int c = 0; c < CP; c++) {
        float4 wv = *reinterpret_cast<const float4*>(g_WCAT + c * PQW + j0);
#pragma unroll
        for (int r = 0; r < 16; r++) {
            float p = sPre[r][c];
            acc[r][0] = fmaf(p, wv.x, acc[r][0]);
            acc[r][1] = fmaf(p, wv.y, acc[r][1]);
            acc[r][2] = fmaf(p, wv.z, acc[r][2]);
            acc[r][3] = fmaf(p, wv.w, acc[r][3]);
        }
    }

    float4 bb = make_float4(0.f, 0.f, 0.f, 0.f);
    if (blockIdx.x == 1) {                  // Q half carries the bias
        bb = *reinterpret_cast<const float4*>(b_r + t * 4);
    }
#pragma unroll
    for (int r = 0; r < 16; r++) {
        float4 o;
        o.x = acc[r][0] + bb.x;
        o.y = acc[r][1] + bb.y;
        o.z = acc[r][2] + bb.z;
        o.w = acc[r][3] + bb.w;
        *reinterpret_cast<float4*>(g_PQ + (rb + r) * PQW + j0) = o;
    }
}

// ---------------- exact KNN: per-row top-36 smallest distances ---------------
// CTA per row; 256 threads; each thread holds 8 distances in registers.
// Selection: packed (dist,idx) key, warp shfl-min + shared atomicMin.
// Tie-break = lower index first (matches jax.lax.top_k).
__global__ void __launch_bounds__(256) knn_kernel(const float* __restrict__ xyz) {
    int n = blockIdx.x;
    int base = (n >> 11) << 11;          // batch start row
    int t = threadIdx.x;
    __shared__ unsigned long long sMin;

    float qx = xyz[n * 3 + 0], qy = xyz[n * 3 + 1], qz = xyz[n * 3 + 2];
    float d2n = g_d2[n];

    int m0 = t * 8;                      // local index base for this thread
    float lv[8];
#pragma unroll
    for (int i = 0; i < 8; i++) {
        int m = base + m0 + i;
        float x = xyz[m * 3 + 0], y = xyz[m * 3 + 1], z = xyz[m * 3 + 2];
        // match einsum accumulation: fma chain over c = 0,1,2
        float inner = __fmaf_rn(z, qz, __fmaf_rn(y, qy, __fmul_rn(x, qx)));
        float A = __fadd_rn(d2n, g_d2[m]);
        lv[i] = __fadd_rn(A, __fmul_rn(-2.0f, inner));
    }

    unsigned long long lb = ~0ull;
#pragma unroll
    for (int i = 0; i < 8; i++) {
        unsigned long long key =
            ((unsigned long long)fkey(lv[i]) << 32) | (unsigned int)(m0 + i);
        lb = min(lb, key);
    }

    if (t == 0) sMin = ~0ull;

    for (int iter = 0; iter < KNN; iter++) {
        __syncthreads();                       // sMin reset visible
        unsigned long long wmin = lb;
#pragma unroll
        for (int off = 16; off >= 1; off >>= 1) {
            unsigned long long o = __shfl_xor_sync(0xffffffffu, wmin, off);
            wmin = min(wmin, o);
        }
        if ((t & 31) == 0) atomicMin(&sMin, wmin);
        __syncthreads();
        unsigned long long wkey = sMin;
        int wm = (int)(wkey & 0xffffffffu);    // local winner index
        __syncthreads();                       // everyone read before reset
        if (t == 0) {
            g_idx[n * KNN + iter] = base + wm;
            sMin = ~0ull;
        }
        if ((wm >> 3) == t) {                  // I own the winner: remove & rescan
            lv[wm & 7] = CUDART_INF_F;
            unsigned long long nb = ~0ull;
#pragma unroll
            for (int i = 0; i < 8; i++) {
                unsigned long long key =
                    ((unsigned long long)fkey(lv[i]) << 32) |
                    (unsigned int)(m0 + i);
                nb = min(nb, key);
            }
            lb = nb;
        }
    }
}

// ---------------- fused main: raw = P[m]+Q[n]; normalize; accumulate; @W_s ---
// CTA per point n; 8 warps; warp w owns d-rows {w, 8+w, 16+w, 24+w}; lane = e.
__global__ void __launch_bounds__(256) main_kernel(const float* __restrict__ W_s,
                                                   const float* __restrict__ b_s,
                                                   float* __restrict__ out) {
    __shared__ float sQ[DD];
    __shared__ float sGV[KNN * DIM];
    __shared__ int   sIdx[KNN];
    __shared__ float sPar[8 * 32];
    __shared__ float sO[32];

    int n = blockIdx.x, t = threadIdx.x;
    if (t < KNN) sIdx[t] = g_idx[n * KNN + t];
    const float* qrow = g_PQ + n * PQW + DD;
    for (int j = t; j < DD; j += 256) sQ[j] = qrow[j];
    __syncthreads();
    for (int q = t; q < KNN * DIM; q += 256) {
        int k = q >> 5, d = q & 31;
        sGV[q] = g_v[sIdx[k] * DIM + d];
    }
    __syncthreads();

    int w = t >> 5, lane = t & 31;
    float acc = 0.0f;

    for (int k = 0; k < KNN; k++) {
        const float* Pr = g_PQ + sIdx[k] * PQW;
        float pv[4];
#pragma unroll
        for (int dr = 0; dr < 4; dr++)
            pv[dr] = Pr[(dr * 8 + w) * 32 + lane];     // coalesced 128B/warp
#pragma unroll
        for (int dr = 0; dr < 4; dr++) {
            int d = dr * 8 + w;
            float raw = pv[dr] + sQ[d * 32 + lane];
            float a = fabsf(raw);
            a += __shfl_xor_sync(0xffffffffu, a, 16);
            a += __shfl_xor_sync(0xffffffffu, a, 8);
            a += __shfl_xor_sync(0xffffffffu, a, 4);
            a += __shfl_xor_sync(0xffffffffu, a, 2);
            a += __shfl_xor_sync(0xffffffffu, a, 1);
            float s = a + 3.2e-6f;                     // 32 * 1e-7 eps term
            float coef = sGV[k * 32 + d] / s;
            acc = fmaf(coef, raw, acc);
        }
    }

    sPar[w * 32 + lane] = acc;
    __syncthreads();
    if (w == 0) {
        float o = 0.0f;
#pragma unroll
        for (int ww = 0; ww < 8; ww++) o += sPar[ww * 32 + lane];
        o *= 5.656854249f;                             // sqrt(32)
        sO[lane] = o;
        __syncwarp();
        float f = b_s[lane];
#pragma unroll
        for (int e = 0; e < 32; e++)
            f = fmaf(sO[e], W_s[e * 32 + lane], f);
        out[n * 32 + lane] = f;
    }
}

// ---------------- tail: second tuple element (scalar N) ----------------------
__global__ void tail_kernel(float* __restrict__ out, int out_size) {
    int i = BN * DIM + blockIdx.x * blockDim.x + threadIdx.x;
    if (i < out_size) out[i] = (float)NPTS;
}

// ---------------- launch -----------------------------------------------------
extern "C" void kernel_launch(void* const* d_in, const int* in_sizes, int n_in,
                              void* d_out, int out_size) {
    const float* feature = (const float*)d_in[0];
    const float* xyz     = (const float*)d_in[1];
    const float* W_r     = (const float*)d_in[2];
    const float* b_r     = (const float*)d_in[3];
    const float* W_v     = (const float*)d_in[4];
    const float* b_v     = (const float*)d_in[5];
    const float* W_s     = (const float*)d_in[6];
    const float* b_s     = (const float*)d_in[7];
    float* out = (float*)d_out;

    prep_pre_d2<<<(BN * CP + 255) / 256, 256>>>(feature, xyz);
    prep_wcat<<<(CP * PQW + 255) / 256, 256>>>(W_r);
    prep_v<<<(BN * DIM + 255) / 256, 256>>>(W_v, b_v);
    gemm_pq<<<dim3(2, BN / 16), 256>>>(b_r);
    knn_kernel<<<BN, 256>>>(xyz);
    main_kernel<<<BN, 256>>>(W_s, b_s, out);

    int rem = out_size - BN * DIM;
    if (rem > 0) tail_kernel<<<(rem + 255) / 256, 256>>>(out, out_size);
}

// round 12
// speedup vs baseline: 1.5893x; 1.5893x over previous
#include <cuda_runtime.h>
#include <math_constants.h>

// Problem constants (fixed for this dataset problem)
#define BATCH 2
#define NPTS  2048
#define BN    (BATCH * NPTS)   // 4096 total points
#define CF    32               // feature channels
#define CP    35               // C + 3
#define DIM   32               // D
#define KNN   36               // k
#define DD    1024             // D*D
#define PQW   2048             // P(1024) | Q(1024)

// ---------------- device scratch (no runtime allocation allowed) -------------
__device__ float g_pre[BN * CP];       // [4096,35] concat(feature,xyz)
__device__ float g_d2[BN];             // squared norms of xyz
__device__ float g_v[BN * DIM];        // relu(pre @ W_v + b_v)
__device__ int   g_idx[BN * KNN];      // global neighbor row indices
__device__ float g_WCAT[CP * PQW];     // [35, 2048] = [W1 | W2-W1]
__device__ float g_PQ[BN * PQW];       // [4096, 2048] = [P | Q] (32 MB)

// ---------------- helpers ----------------------------------------------------
__device__ __forceinline__ unsigned int fkey(float v) {
    unsigned int u = __float_as_uint(v);
    return (u & 0x80000000u) ? ~u : (u | 0x80000000u);   // order-preserving map
}

// ---------------- prep: pre = concat(feature,xyz); d2 = sum(xyz^2) -----------
__global__ void prep_pre_d2(const float* __restrict__ feature,
                            const float* __restrict__ xyz) {
    int gid = blockIdx.x * blockDim.x + threadIdx.x;
    if (gid < BN * CP) {
        int n = gid / CP, c = gid - n * CP;
        g_pre[gid] = (c < CF) ? feature[n * CF + c] : xyz[n * 3 + (c - CF)];
    }
    if (gid < BN) {
        float x = xyz[gid * 3 + 0], y = xyz[gid * 3 + 1], z = xyz[gid * 3 + 2];
        g_d2[gid] = __fadd_rn(__fadd_rn(__fmul_rn(x, x), __fmul_rn(y, y)),
                              __fmul_rn(z, z));
    }
}

// ---------------- prep: WCAT = [W1 | W2 - W1] --------------------------------
__global__ void prep_wcat(const float* __restrict__ W_r) {
    int gid = blockIdx.x * blockDim.x + threadIdx.x;
    if (gid < CP * PQW) {
        int c = gid / PQW, j = gid - c * PQW;
        if (j < DD) {
            g_WCAT[gid] = W_r[c * DD + j];
        } else {
            int jj = j - DD;
            g_WCAT[gid] = W_r[(CP + c) * DD + jj] - W_r[c * DD + jj];
        }
    }
}

// ---------------- prep: v = relu(pre @ W_v + b_v) ----------------------------
__global__ void prep_v(const float* __restrict__ W_v,
                       const float* __restrict__ b_v) {
    int gid = blockIdx.x * blockDim.x + threadIdx.x;
    if (gid < BN * DIM) {
        int n = gid >> 5, d = gid & 31;
        const float* pr = g_pre + n * CP;
        float acc = b_v[d];
#pragma unroll
        for (int c = 0; c < CP; c++)
            acc = fmaf(pr[c], W_v[c * DIM + d], acc);
        g_v[gid] = fmaxf(acc, 0.0f);
    }
}

// ---------------- PQ = pre @ WCAT (+ b_r on Q half) --------------------------
// CTA: 8 rows x 1024 cols; 256 threads; thread owns 4 CONSECUTIVE cols x 8
// rows (~60 regs -> ~4 CTAs/SM). LDG.128 / STG.128 throughout.
// FIX R3->R4: 8*CP = 280 > 256, so staging MUST be a strided loop.
__global__ void __launch_bounds__(256) gemm_pq(const float* __restrict__ b_r) {
    __shared__ float sPre[8][CP + 1];
    int t = threadIdx.x;
    int rb = blockIdx.y * 8;
    for (int q = t; q < 8 * CP; q += 256) {     // strided: covers all 280
        int r = q / CP, c = q - r * CP;
        sPre[r][c] = g_pre[(rb + r) * CP + c];
    }
    __syncthreads();

    int j0 = blockIdx.x * 1024 + t * 4;    // 4 consecutive columns
    float acc[8][4];
#pragma unroll
    for (int r = 0; r < 8; r++)
#pragma unroll
        for (int q = 0; q < 4; q++) acc[r][q] = 0.0f;

#pragma unroll 5
    for (int c = 0; c < CP; c++) {
        float4 wv = *reinterpret_cast<const float4*>(g_WCAT + c * PQW + j0);
#pragma unroll
        for (int r = 0; r < 8; r++) {
            float p = sPre[r][c];
            acc[r][0] = fmaf(p, wv.x, acc[r][0]);
            acc[r][1] = fmaf(p, wv.y, acc[r][1]);
            acc[r][2] = fmaf(p, wv.z, acc[r][2]);
            acc[r][3] = fmaf(p, wv.w, acc[r][3]);
        }
    }

    float4 bb = make_float4(0.f, 0.f, 0.f, 0.f);
    if (blockIdx.x == 1) {                  // Q half carries the bias
        bb = *reinterpret_cast<const float4*>(b_r + t * 4);
    }
#pragma unroll
    for (int r = 0; r < 8; r++) {
        float4 o;
        o.x = acc[r][0] + bb.x;
        o.y = acc[r][1] + bb.y;
        o.z = acc[r][2] + bb.z;
        o.w = acc[r][3] + bb.w;
        *reinterpret_cast<float4*>(g_PQ + (rb + r) * PQW + j0) = o;
    }
}

// ---------------- exact KNN: per-row top-36 smallest distances ---------------
// (unchanged — isolate main_kernel delta)
__global__ void __launch_bounds__(256) knn_kernel(const float* __restrict__ xyz) {
    int n = blockIdx.x;
    int base = (n >> 11) << 11;          // batch start row
    int t = threadIdx.x;
    __shared__ unsigned long long sMin;

    float qx = xyz[n * 3 + 0], qy = xyz[n * 3 + 1], qz = xyz[n * 3 + 2];
    float d2n = g_d2[n];

    int m0 = t * 8;
    float lv[8];
#pragma unroll
    for (int i = 0; i < 8; i++) {
        int m = base + m0 + i;
        float x = xyz[m * 3 + 0], y = xyz[m * 3 + 1], z = xyz[m * 3 + 2];
        float inner = __fmaf_rn(z, qz, __fmaf_rn(y, qy, __fmul_rn(x, qx)));
        float A = __fadd_rn(d2n, g_d2[m]);
        lv[i] = __fadd_rn(A, __fmul_rn(-2.0f, inner));
    }

    unsigned long long lb = ~0ull;
#pragma unroll
    for (int i = 0; i < 8; i++) {
        unsigned long long key =
            ((unsigned long long)fkey(lv[i]) << 32) | (unsigned int)(m0 + i);
        lb = min(lb, key);
    }

    if (t == 0) sMin = ~0ull;

    for (int iter = 0; iter < KNN; iter++) {
        __syncthreads();
        unsigned long long wmin = lb;
#pragma unroll
        for (int off = 16; off >= 1; off >>= 1) {
            unsigned long long o = __shfl_xor_sync(0xffffffffu, wmin, off);
            wmin = min(wmin, o);
        }
        if ((t & 31) == 0) atomicMin(&sMin, wmin);
        __syncthreads();
        unsigned long long wkey = sMin;
        int wm = (int)(wkey & 0xffffffffu);
        __syncthreads();
        if (t == 0) {
            g_idx[n * KNN + iter] = base + wm;
            sMin = ~0ull;
        }
        if ((wm >> 3) == t) {
            lv[wm & 7] = CUDART_INF_F;
            unsigned long long nb = ~0ull;
#pragma unroll
            for (int i = 0; i < 8; i++) {
                unsigned long long key =
                    ((unsigned long long)fkey(lv[i]) << 32) |
                    (unsigned int)(m0 + i);
                nb = min(nb, key);
            }
            lb = nb;
        }
    }
}

// ---------------- fused main v2 ----------------------------------------------
// CTA per point n; 256 threads; thread t -> (d = t>>3, ec = t&7,
// e = ec*4 .. ec*4+3). P row staged to smem (double-buffered, 1 bar/iter).
// Row-sum: 3 local |adds| + 3-step shfl over 8 lanes. Fast division.
__global__ void __launch_bounds__(256) main_kernel(const float* __restrict__ W_s,
                                                   const float* __restrict__ b_s,
                                                   float* __restrict__ out) {
    __shared__ float sQ[DD];
    __shared__ float sP[2][DD];            // double-buffered gathered P row
    __shared__ float sGV[KNN * DIM];
    __shared__ int   sIdx[KNN];
    __shared__ float sO[32];

    int n = blockIdx.x, t = threadIdx.x;
    if (t < KNN) sIdx[t] = g_idx[n * KNN + t];
    // Q row: 256 x float4, coalesced
    reinterpret_cast<float4*>(sQ)[t] =
        reinterpret_cast<const float4*>(g_PQ + n * PQW + DD)[t];
    __syncthreads();                       // sQ + sIdx visible

    int d  = t >> 3;                       // d-row 0..31
    int ec = t & 7;                        // e chunk
    float4 qv = *reinterpret_cast<const float4*>(sQ + d * 32 + ec * 4);

    // gather v for all neighbors (coalesced per warp)
    for (int q = t; q < KNN * DIM; q += 256) {
        int k = q >> 5, dd = q & 31;
        sGV[q] = g_v[sIdx[k] * DIM + dd];
    }
    // prologue: stage P row of neighbor 0
    reinterpret_cast<float4*>(sP[0])[t] =
        reinterpret_cast<const float4*>(g_PQ + (size_t)sIdx[0] * PQW)[t];

    float p0 = 0.f, p1 = 0.f, p2 = 0.f, p3 = 0.f;  // partial acc (4 e's)

    for (int k = 0; k < KNN; k++) {
        __syncthreads();                   // buf[k&1] staged; prev consumes done
        if (k + 1 < KNN) {                 // prefetch next neighbor row
            reinterpret_cast<float4*>(sP[(k + 1) & 1])[t] =
                reinterpret_cast<const float4*>(g_PQ + (size_t)sIdx[k + 1] * PQW)[t];
        }
        float4 pv = *reinterpret_cast<const float4*>(sP[k & 1] + d * 32 + ec * 4);
        float r0 = pv.x + qv.x;
        float r1 = pv.y + qv.y;
        float r2 = pv.z + qv.z;
        float r3 = pv.w + qv.w;
        float a = fabsf(r0) + fabsf(r1) + fabsf(r2) + fabsf(r3);
        a += __shfl_xor_sync(0xffffffffu, a, 1);
        a += __shfl_xor_sync(0xffffffffu, a, 2);
        a += __shfl_xor_sync(0xffffffffu, a, 4);   // sum over 8 lanes = full d-row
        float s = a + 3.2e-6f;                     // 32 * 1e-7
        float coef = __fdividef(sGV[k * 32 + d], s);
        p0 = fmaf(coef, r0, p0);
        p1 = fmaf(coef, r1, p1);
        p2 = fmaf(coef, r2, p2);
        p3 = fmaf(coef, r3, p3);
    }

    // cross-d reduction: overlay sPar[32][36] on sP (1152 <= 2048 floats)
    float* sPar = &sP[0][0];
    __syncthreads();                       // all k=35 consumes done before overlay
    *reinterpret_cast<float4*>(sPar + d * 36 + ec * 4) = make_float4(p0, p1, p2, p3);
    __syncthreads();

    if (t < 32) {                          // warp 0: t = e
        float o = 0.0f;
#pragma unroll
        for (int dd = 0; dd < 32; dd++)
            o += sPar[dd * 36 + t];        // stride 36 -> conflict-free
        o *= 5.656854249f;                 // sqrt(32)
        sO[t] = o;
        __syncwarp(0xffffffffu);
        float f = b_s[t];
#pragma unroll
        for (int e = 0; e < 32; e++)
            f = fmaf(sO[e], W_s[e * 32 + t], f);
        out[n * 32 + t] = f;
    }
}

// ---------------- tail: second tuple element (scalar N) ----------------------
__global__ void tail_kernel(float* __restrict__ out, int out_size) {
    int i = BN * DIM + blockIdx.x * blockDim.x + threadIdx.x;
    if (i < out_size) out[i] = (float)NPTS;
}

// ---------------- launch -----------------------------------------------------
extern "C" void kernel_launch(void* const* d_in, const int* in_sizes, int n_in,
                              void* d_out, int out_size) {
    const float* feature = (const float*)d_in[0];
    const float* xyz     = (const float*)d_in[1];
    const float* W_r     = (const float*)d_in[2];
    const float* b_r     = (const float*)d_in[3];
    const float* W_v     = (const float*)d_in[4];
    const float* b_v     = (const float*)d_in[5];
    const float* W_s     = (const float*)d_in[6];
    const float* b_s     = (const float*)d_in[7];
    float* out = (float*)d_out;

    prep_pre_d2<<<(BN * CP + 255) / 256, 256>>>(feature, xyz);
    prep_wcat<<<(CP * PQW + 255) / 256, 256>>>(W_r);
    prep_v<<<(BN * DIM + 255) / 256, 256>>>(W_v, b_v);
    gemm_pq<<<dim3(2, BN / 8), 256>>>(b_r);
    knn_kernel<<<BN, 256>>>(xyz);
    main_kernel<<<BN, 256>>>(W_s, b_s, out);

    int rem = out_size - BN * DIM;
    if (rem > 0) tail_kernel<<<(rem + 255) / 256, 256>>>(out, out_size);
}